// round 1
// baseline (speedup 1.0000x reference)
#include <cuda_runtime.h>
#include <math.h>

// Problem constants
#define BATCH 1024
#define WARPS_PER_BLOCK 8
#define BLOCK (WARPS_PER_BLOCK * 32)
#define MAX_STEPS 128

// Dopri5 tableau (computed in double, stored as float, matching f32 JAX constants)
__device__ __constant__ float dummy_pad[1];

// Folded decoder: w = pW3^T @ dW (64), c = dW . pb3
__device__ float g_w[64];
__device__ float g_c[1];

__global__ void precompute_kernel(const float* __restrict__ dW,
                                  const float* __restrict__ pW3,
                                  const float* __restrict__ pb3) {
    int j = threadIdx.x;  // 0..63
    float acc = 0.0f;
    #pragma unroll 8
    for (int i = 0; i < 64; ++i) acc = fmaf(dW[i], pW3[i * 64 + j], acc);
    g_w[j] = acc;
    if (j == 0) {
        float c = 0.0f;
        #pragma unroll 8
        for (int i = 0; i < 64; ++i) c = fmaf(dW[i], pb3[i], c);
        g_c[0] = c;
    }
}

// theta MLP: 2 -> 32 (tanh) -> 32 (tanh) -> 1. One lane per hidden neuron.
// Returns tW3 . h2 (bias tb3 added by caller). All lanes get the result.
__device__ __forceinline__ float theta_eval(float taus, float ys,
                                            float ta, float tbw, float tb1r,
                                            float tb2r, float tw3r,
                                            const float* __restrict__ sT2T,
                                            int lane) {
    float h = tanhf(fmaf(ta, taus, fmaf(tbw, ys, tb1r)));
    float a0 = tb2r, a1 = 0.0f, a2 = 0.0f, a3 = 0.0f;
    #pragma unroll
    for (int k = 0; k < 32; k += 4) {
        float h0 = __shfl_sync(0xffffffffu, h, k + 0);
        float h1 = __shfl_sync(0xffffffffu, h, k + 1);
        float h2s = __shfl_sync(0xffffffffu, h, k + 2);
        float h3 = __shfl_sync(0xffffffffu, h, k + 3);
        a0 = fmaf(sT2T[(k + 0) * 33 + lane], h0, a0);
        a1 = fmaf(sT2T[(k + 1) * 33 + lane], h1, a1);
        a2 = fmaf(sT2T[(k + 2) * 33 + lane], h2s, a2);
        a3 = fmaf(sT2T[(k + 3) * 33 + lane], h3, a3);
    }
    float h2 = tanhf(((a0 + a1) + (a2 + a3)));
    float v = tw3r * h2;
    #pragma unroll
    for (int off = 16; off; off >>= 1)
        v += __shfl_xor_sync(0xffffffffu, v, off);
    return v;
}

__global__ void __launch_bounds__(BLOCK, 1)
neural_ode_kernel(const float* __restrict__ t,
                  const float* __restrict__ pW1, const float* __restrict__ pb1,
                  const float* __restrict__ pW2, const float* __restrict__ pb2,
                  const float* __restrict__ db,
                  const float* __restrict__ tW1, const float* __restrict__ tb1,
                  const float* __restrict__ tW2, const float* __restrict__ tb2,
                  const float* __restrict__ tW3, const float* __restrict__ tb3,
                  float* __restrict__ out) {
    // Shared weight staging (padded to avoid bank conflicts)
    __shared__ float sW2T[64 * 65];   // sW2T[k*65 + j] = pW2[j][k]
    __shared__ float sT2T[32 * 33];   // sT2T[k*33 + j] = tW2[j][k]
    __shared__ float sW1a[64], sW1b[64], sPb1[64], sPb2[64], sw[64];
    __shared__ float sT1a[32], sT1b[32], sTb1[32], sTb2[32], sTw3[32];
    __shared__ float sScal[3];        // c_fold, db0, tb3_0

    int tid = threadIdx.x;
    for (int idx = tid; idx < 4096; idx += BLOCK) {
        int j = idx >> 6, k = idx & 63;
        sW2T[k * 65 + j] = pW2[idx];
    }
    for (int idx = tid; idx < 1024; idx += BLOCK) {
        int j = idx >> 5, k = idx & 31;
        sT2T[k * 33 + j] = tW2[idx];
    }
    if (tid < 64) {
        sW1a[tid] = pW1[2 * tid];
        sW1b[tid] = pW1[2 * tid + 1];
        sPb1[tid] = pb1[tid];
        sPb2[tid] = pb2[tid];
        sw[tid]   = g_w[tid];
    }
    if (tid < 32) {
        sT1a[tid] = tW1[2 * tid];
        sT1b[tid] = tW1[2 * tid + 1];
        sTb1[tid] = tb1[tid];
        sTb2[tid] = tb2[tid];
        sTw3[tid] = tW3[tid];
    }
    if (tid == 0) {
        sScal[0] = g_c[0];
        sScal[1] = db[0];
        sScal[2] = tb3[0];
    }
    __syncthreads();

    int warp = tid >> 5, lane = tid & 31;
    int b = blockIdx.x * WARPS_PER_BLOCK + warp;

    // Hoist per-lane weights to registers
    float w1a_lo = sW1a[lane],       w1b_lo = sW1b[lane];
    float w1a_hi = sW1a[lane + 32],  w1b_hi = sW1b[lane + 32];
    float b1_lo  = sPb1[lane],       b1_hi  = sPb1[lane + 32];
    float b2_lo  = sPb2[lane],       b2_hi  = sPb2[lane + 32];
    float w_lo   = sw[lane],         w_hi   = sw[lane + 32];
    float ta  = sT1a[lane], tbw = sT1b[lane], tb1r = sTb1[lane];
    float tb2r = sTb2[lane], tw3r = sTw3[lane];
    float cfold = sScal[0], db0 = sScal[1], tb30 = sScal[2];

    // Tableau constants (f32 of the exact double values)
    const float C2 = 0.2f, C3 = 0.3f, C4 = 0.8f, C5 = (float)(8.0 / 9.0);
    const float A21 = 0.2f;
    const float A31 = (float)(3.0 / 40.0),   A32 = (float)(9.0 / 40.0);
    const float A41 = (float)(44.0 / 45.0),  A42 = (float)(-56.0 / 15.0), A43 = (float)(32.0 / 9.0);
    const float A51 = (float)(19372.0 / 6561.0), A52 = (float)(-25360.0 / 2187.0);
    const float A53 = (float)(64448.0 / 6561.0), A54 = (float)(-212.0 / 729.0);
    const float A61 = (float)(9017.0 / 3168.0),  A62 = (float)(-355.0 / 33.0);
    const float A63 = (float)(46732.0 / 5247.0), A64 = (float)(49.0 / 176.0);
    const float A65 = (float)(-5103.0 / 18656.0);
    const float B1 = (float)(35.0 / 384.0), B3 = (float)(500.0 / 1113.0);
    const float B4 = (float)(125.0 / 192.0), B5 = (float)(-2187.0 / 6784.0);
    const float B6 = (float)(11.0 / 84.0);
    const float E1 = (float)(35.0 / 384.0 - 5179.0 / 57600.0);
    const float E3 = (float)(500.0 / 1113.0 - 7571.0 / 16695.0);
    const float E4 = (float)(125.0 / 192.0 - 393.0 / 640.0);
    const float E5 = (float)(-2187.0 / 6784.0 + 92097.0 / 339200.0);
    const float E6 = (float)(11.0 / 84.0 - 187.0 / 2100.0);
    const float E7 = (float)(-1.0 / 40.0);
    const float RTOL = 1e-3f, ATOL = 1e-6f;
    const float SAFETY = 0.9f, FMIN = 0.2f, FMAX = 10.0f;

    float t1 = t[b];
    float tau = 0.0f, y = 0.0f, dt = 0.01f;

    for (int it = 0; it < MAX_STEPS; ++it) {
        float remaining = t1 - tau;
        if (remaining <= 1e-10f) break;
        float dt_eff = fminf(dt, remaining);

        // Stage taus (6 distinct; stages 6 & 7 share tau+dt)
        float taus[6];
        taus[0] = tau;
        taus[1] = tau + C2 * dt_eff;
        taus[2] = tau + C3 * dt_eff;
        taus[3] = tau + C4 * dt_eff;
        taus[4] = tau + C5 * dt_eff;
        taus[5] = tau + dt_eff;

        // ---- Batched phi for all 6 taus: g[s] = w . tanh(W2 tanh(W1 x + b1) + b2) + c
        float h1lo[6], h1hi[6];
        #pragma unroll
        for (int s = 0; s < 6; ++s) {
            h1lo[s] = tanhf(fmaf(w1a_lo, t1, fmaf(w1b_lo, taus[s], b1_lo)));
            h1hi[s] = tanhf(fmaf(w1a_hi, t1, fmaf(w1b_hi, taus[s], b1_hi)));
        }
        float acc_lo[6], acc_hi[6];
        #pragma unroll
        for (int s = 0; s < 6; ++s) { acc_lo[s] = b2_lo; acc_hi[s] = b2_hi; }

        #pragma unroll 4
        for (int k = 0; k < 32; ++k) {
            float alo[6], ahi[6];
            #pragma unroll
            for (int s = 0; s < 6; ++s) {
                alo[s] = __shfl_sync(0xffffffffu, h1lo[s], k);
                ahi[s] = __shfl_sync(0xffffffffu, h1hi[s], k);
            }
            float wA = sW2T[k * 65 + lane];
            float wB = sW2T[(k + 32) * 65 + lane];
            float wC = sW2T[k * 65 + lane + 32];
            float wD = sW2T[(k + 32) * 65 + lane + 32];
            #pragma unroll
            for (int s = 0; s < 6; ++s) {
                acc_lo[s] = fmaf(wA, alo[s], fmaf(wB, ahi[s], acc_lo[s]));
                acc_hi[s] = fmaf(wC, alo[s], fmaf(wD, ahi[s], acc_hi[s]));
            }
        }
        float g[6];
        #pragma unroll
        for (int s = 0; s < 6; ++s) {
            float v = fmaf(w_lo, tanhf(acc_lo[s]), w_hi * tanhf(acc_hi[s]));
            #pragma unroll
            for (int off = 16; off; off >>= 1)
                v += __shfl_xor_sync(0xffffffffu, v, off);
            g[s] = v + cfold;
        }

        // ---- Sequential theta stages
        float f1 = theta_eval(taus[0], y, ta, tbw, tb1r, tb2r, tw3r, sT2T, lane) + tb30;
        float k1 = fmaf(g[0], f1, db0);

        float y2 = fmaf(dt_eff, A21 * k1, y);
        float f2 = theta_eval(taus[1], y2, ta, tbw, tb1r, tb2r, tw3r, sT2T, lane) + tb30;
        float k2 = fmaf(g[1], f2, db0);

        float y3 = fmaf(dt_eff, fmaf(A31, k1, A32 * k2), y);
        float f3 = theta_eval(taus[2], y3, ta, tbw, tb1r, tb2r, tw3r, sT2T, lane) + tb30;
        float k3 = fmaf(g[2], f3, db0);

        float y4 = fmaf(dt_eff, fmaf(A41, k1, fmaf(A42, k2, A43 * k3)), y);
        float f4 = theta_eval(taus[3], y4, ta, tbw, tb1r, tb2r, tw3r, sT2T, lane) + tb30;
        float k4 = fmaf(g[3], f4, db0);

        float y5i = fmaf(dt_eff, fmaf(A51, k1, fmaf(A52, k2, fmaf(A53, k3, A54 * k4))), y);
        float f5 = theta_eval(taus[4], y5i, ta, tbw, tb1r, tb2r, tw3r, sT2T, lane) + tb30;
        float k5 = fmaf(g[4], f5, db0);

        float y6 = fmaf(dt_eff, fmaf(A61, k1, fmaf(A62, k2, fmaf(A63, k3, fmaf(A64, k4, A65 * k5)))), y);
        float f6 = theta_eval(taus[5], y6, ta, tbw, tb1r, tb2r, tw3r, sT2T, lane) + tb30;
        float k6 = fmaf(g[5], f6, db0);

        float y5 = fmaf(dt_eff,
                        fmaf(B1, k1, fmaf(B3, k3, fmaf(B4, k4, fmaf(B5, k5, B6 * k6)))),
                        y);
        float f7 = theta_eval(taus[5], y5, ta, tbw, tb1r, tb2r, tw3r, sT2T, lane) + tb30;
        float k7 = fmaf(g[5], f7, db0);

        float err = dt_eff *
            fmaf(E1, k1, fmaf(E3, k3, fmaf(E4, k4, fmaf(E5, k5, fmaf(E6, k6, E7 * k7)))));
        float scale = fmaf(RTOL, fmaxf(fabsf(y), fabsf(y5)), ATOL);
        float r = err / scale;
        float err_norm = sqrtf(fmaf(r, r, 1e-30f));

        bool accept = (err_norm <= 1.0f);
        float factor = SAFETY * powf(fmaxf(err_norm, 1e-10f), -0.2f);
        factor = fminf(fmaxf(factor, FMIN), FMAX);

        if (accept) {
            tau = tau + dt_eff;
            y = y5;
        }
        dt = fmaxf(dt_eff * factor, 1e-8f);
    }

    if (lane == 0) out[b] = y;
}

extern "C" void kernel_launch(void* const* d_in, const int* in_sizes, int n_in,
                              void* d_out, int out_size) {
    const float* t    = (const float*)d_in[0];
    const float* pW1  = (const float*)d_in[1];
    const float* pb1  = (const float*)d_in[2];
    const float* pW2  = (const float*)d_in[3];
    const float* pb2  = (const float*)d_in[4];
    const float* pW3  = (const float*)d_in[5];
    const float* pb3  = (const float*)d_in[6];
    const float* dW   = (const float*)d_in[7];
    const float* db   = (const float*)d_in[8];
    const float* tW1  = (const float*)d_in[9];
    const float* tb1  = (const float*)d_in[10];
    const float* tW2  = (const float*)d_in[11];
    const float* tb2  = (const float*)d_in[12];
    const float* tW3  = (const float*)d_in[13];
    const float* tb3  = (const float*)d_in[14];
    float* out = (float*)d_out;

    precompute_kernel<<<1, 64>>>(dW, pW3, pb3);
    neural_ode_kernel<<<BATCH / WARPS_PER_BLOCK, BLOCK>>>(
        t, pW1, pb1, pW2, pb2, db, tW1, tb1, tW2, tb2, tW3, tb3, out);
}